// round 7
// baseline (speedup 1.0000x reference)
#include <cuda_runtime.h>
#include <cstdint>

// Problem constants (fixed shapes for this problem instance)
#define N_MASKS 128
#define HM 28
#define WM 28
#define IMG_H 800
#define IMG_W 1280
#define IN_W 1184.0f
#define IN_H 736.0f
#define ROWS_PER_BLOCK 4

// Block = 4 consecutive rows of one mask. 320 threads, thread t owns pixels
// [4t, 4t+3] in each of the 4 rows -> 4x STG.128 per thread. Per-mask affine
// params computed in-kernel (boxes are 2KB, L1-resident) -- no prologue launch.
__global__ void __launch_bounds__(320)
paste_kernel(const float* __restrict__ masks,
             const float* __restrict__ boxes,
             float* __restrict__ out) {
    const int n  = blockIdx.y;
    const int y0 = blockIdx.x * ROWS_PER_BLOCK;
    const int x4 = threadIdx.x * 4;

    // ---- per-mask affine params: px = ax*(x+0.5)+bx, py = ay*(y+0.5)+by ----
    const float sx = (float)IMG_W / IN_W;
    const float sy = (float)IMG_H / IN_H;
    float bx0 = fminf(fmaxf(__ldg(boxes + 4 * n + 0) * sx, 0.0f), (float)IMG_W);
    float by0 = fminf(fmaxf(__ldg(boxes + 4 * n + 1) * sy, 0.0f), (float)IMG_H);
    float bx1 = fminf(fmaxf(__ldg(boxes + 4 * n + 2) * sx, 0.0f), (float)IMG_W);
    float by1 = fminf(fmaxf(__ldg(boxes + 4 * n + 3) * sy, 0.0f), (float)IMG_H);
    float ax = (float)WM / (bx1 - bx0);
    float ay = (float)HM / (by1 - by0);
    float bx = -bx0 * ax - 0.5f;
    float by = -by0 * ay - 0.5f;

    float* dst = out + ((size_t)n * IMG_H + y0) * IMG_W + x4;
    const float4 zero = make_float4(0.f, 0.f, 0.f, 0.f);

    // Support tests (ax, ay > 0 so coords are monotone across the tile)
    float py0 = ay * ((float)y0 + 0.5f) + by;
    float py3 = py0 + 3.0f * ay;
    float px0 = ax * ((float)x4 + 0.5f) + bx;
    float px3 = px0 + 3.0f * ax;
    bool active = (py3 > -1.0f) & (py0 < (float)HM) &
                  (px3 > -1.0f) & (px0 < (float)WM);

    if (!active) {
        // Fast path: 4 independent streaming zero stores (MLP=4).
#pragma unroll
        for (int r = 0; r < ROWS_PER_BLOCK; r++)
            __stcs(reinterpret_cast<float4*>(dst + (size_t)r * IMG_W), zero);
        return;
    }

    // ---- horizontal precompute (shared by all 4 rows) ----
    int   ix0[4], ix1[4];
    float w0[4], w1[4];
#pragma unroll
    for (int k = 0; k < 4; k++) {
        float px  = px0 + (float)k * ax;
        float fx  = floorf(px);
        int   ix  = (int)fx;
        float wx1 = px - fx;
        float wx0 = 1.0f - wx1;
        bool inr = (px > -1.0f) & (px < (float)WM);
        bool vx0 = inr & (ix >= 0);
        bool vx1 = inr & (ix + 1 < WM);
        w0[k]  = vx0 ? wx0 : 0.0f;
        w1[k]  = vx1 ? wx1 : 0.0f;
        ix0[k] = min(max(ix, 0), WM - 1);
        ix1[k] = min(max(ix + 1, 0), WM - 1);
    }

    const float* mbase = masks + (size_t)n * (HM * WM);

#pragma unroll
    for (int r = 0; r < ROWS_PER_BLOCK; r++) {
        float py  = py0 + (float)r * ay;
        float fy  = floorf(py);
        int   iy  = (int)fy;
        float wy1 = py - fy;
        float wy0 = 1.0f - wy1;
        bool inr = (py > -1.0f) & (py < (float)HM);
        float wr0 = (inr & (iy >= 0))     ? wy0 : 0.0f;
        float wr1 = (inr & (iy + 1 < HM)) ? wy1 : 0.0f;
        const float* r0 = mbase + min(max(iy, 0), HM - 1) * WM;
        const float* r1 = mbase + min(max(iy + 1, 0), HM - 1) * WM;

        float res[4];
#pragma unroll
        for (int k = 0; k < 4; k++) {
            float top = w0[k] * __ldg(r0 + ix0[k]) + w1[k] * __ldg(r0 + ix1[k]);
            float bot = w0[k] * __ldg(r1 + ix0[k]) + w1[k] * __ldg(r1 + ix1[k]);
            res[k] = wr0 * top + wr1 * bot;
        }
        __stcs(reinterpret_cast<float4*>(dst + (size_t)r * IMG_W),
               make_float4(res[0], res[1], res[2], res[3]));
    }
}

extern "C" void kernel_launch(void* const* d_in, const int* in_sizes, int n_in,
                              void* d_out, int out_size) {
    const float* masks = (const float*)d_in[0];
    const float* boxes = (const float*)d_in[1];
    float* out = (float*)d_out;

    dim3 grid(IMG_H / ROWS_PER_BLOCK, N_MASKS);   // (200, 128)
    paste_kernel<<<grid, 320>>>(masks, boxes, out);
}

// round 8
// speedup vs baseline: 1.4237x; 1.4237x over previous
#include <cuda_runtime.h>
#include <cstdint>

// Problem constants (fixed shapes for this problem instance)
#define N_MASKS 128
#define HM 28
#define WM 28
#define IMG_H 800
#define IMG_W 1280
#define IN_W 1184.0f
#define IN_H 736.0f
#define ROWS_PER_BLOCK 4

// Block = 4 consecutive rows of one mask. 320 threads, thread t owns pixels
// [4t, 4t+3] in each of the 4 rows -> 4x STG.128 per thread.
// Per-mask affine params computed ONCE per block (thread 0, 2x MUFU.RCP) into
// smem -- fused launch without the per-thread MUFU flood that sank R6.
__global__ void __launch_bounds__(320)
paste_kernel(const float* __restrict__ masks,
             const float* __restrict__ boxes,
             float* __restrict__ out) {
    const int n  = blockIdx.y;
    const int y0 = blockIdx.x * ROWS_PER_BLOCK;
    const int x4 = threadIdx.x * 4;

    __shared__ float4 s_prm;   // ax, bx, ay, by
    if (threadIdx.x == 0) {
        const float sx = (float)IMG_W / IN_W;
        const float sy = (float)IMG_H / IN_H;
        float bx0 = fminf(fmaxf(__ldg(boxes + 4 * n + 0) * sx, 0.0f), (float)IMG_W);
        float by0 = fminf(fmaxf(__ldg(boxes + 4 * n + 1) * sy, 0.0f), (float)IMG_H);
        float bx1 = fminf(fmaxf(__ldg(boxes + 4 * n + 2) * sx, 0.0f), (float)IMG_W);
        float by1 = fminf(fmaxf(__ldg(boxes + 4 * n + 3) * sy, 0.0f), (float)IMG_H);
        float ax = (float)WM / (bx1 - bx0);
        float ay = (float)HM / (by1 - by0);
        s_prm = make_float4(ax, -bx0 * ax - 0.5f, ay, -by0 * ay - 0.5f);
    }
    __syncthreads();
    const float ax = s_prm.x, bx = s_prm.y, ay = s_prm.z, by = s_prm.w;

    float* dst = out + ((size_t)n * IMG_H + y0) * IMG_W + x4;
    const float4 zero = make_float4(0.f, 0.f, 0.f, 0.f);

    // Support tests (ax, ay > 0 so coords are monotone across the tile)
    float py0 = ay * ((float)y0 + 0.5f) + by;
    float py3 = py0 + 3.0f * ay;
    float px0 = ax * ((float)x4 + 0.5f) + bx;
    float px3 = px0 + 3.0f * ax;
    bool active = (py3 > -1.0f) & (py0 < (float)HM) &
                  (px3 > -1.0f) & (px0 < (float)WM);

    if (!active) {
        // Fast path: 4 independent streaming zero stores (MLP=4).
#pragma unroll
        for (int r = 0; r < ROWS_PER_BLOCK; r++)
            __stcs(reinterpret_cast<float4*>(dst + (size_t)r * IMG_W), zero);
        return;
    }

    // ---- horizontal precompute (shared by all 4 rows) ----
    int   ix0[4], ix1[4];
    float w0[4], w1[4];
#pragma unroll
    for (int k = 0; k < 4; k++) {
        float px  = px0 + (float)k * ax;
        float fx  = floorf(px);
        int   ix  = (int)fx;
        float wx1 = px - fx;
        float wx0 = 1.0f - wx1;
        bool inr = (px > -1.0f) & (px < (float)WM);
        bool vx0 = inr & (ix >= 0);
        bool vx1 = inr & (ix + 1 < WM);
        w0[k]  = vx0 ? wx0 : 0.0f;
        w1[k]  = vx1 ? wx1 : 0.0f;
        ix0[k] = min(max(ix, 0), WM - 1);
        ix1[k] = min(max(ix + 1, 0), WM - 1);
    }

    const float* mbase = masks + (size_t)n * (HM * WM);

#pragma unroll
    for (int r = 0; r < ROWS_PER_BLOCK; r++) {
        float py  = py0 + (float)r * ay;
        float fy  = floorf(py);
        int   iy  = (int)fy;
        float wy1 = py - fy;
        float wy0 = 1.0f - wy1;
        bool inr = (py > -1.0f) & (py < (float)HM);
        float wr0 = (inr & (iy >= 0))     ? wy0 : 0.0f;
        float wr1 = (inr & (iy + 1 < HM)) ? wy1 : 0.0f;
        const float* r0 = mbase + min(max(iy, 0), HM - 1) * WM;
        const float* r1 = mbase + min(max(iy + 1, 0), HM - 1) * WM;

        float res[4];
#pragma unroll
        for (int k = 0; k < 4; k++) {
            float top = w0[k] * __ldg(r0 + ix0[k]) + w1[k] * __ldg(r0 + ix1[k]);
            float bot = w0[k] * __ldg(r1 + ix0[k]) + w1[k] * __ldg(r1 + ix1[k]);
            res[k] = wr0 * top + wr1 * bot;
        }
        __stcs(reinterpret_cast<float4*>(dst + (size_t)r * IMG_W),
               make_float4(res[0], res[1], res[2], res[3]));
    }
}

extern "C" void kernel_launch(void* const* d_in, const int* in_sizes, int n_in,
                              void* d_out, int out_size) {
    const float* masks = (const float*)d_in[0];
    const float* boxes = (const float*)d_in[1];
    float* out = (float*)d_out;

    dim3 grid(IMG_H / ROWS_PER_BLOCK, N_MASKS);   // (200, 128)
    paste_kernel<<<grid, 320>>>(masks, boxes, out);
}